// round 13
// baseline (speedup 1.0000x reference)
#include <cuda_runtime.h>
#include <cstdint>

#define N_NODES 100000
#define N_EDGES 1000000
#define DIM 64
#define BN_EPS 1e-5f
#define CAP 96                                          // max in-degree bucket

#define GEMM_BM 128                                     // nodes per gemm tile
#define GEMM_NBLK ((N_NODES + GEMM_BM - 1) / GEMM_BM)   // 782

typedef unsigned long long u64;

// packed fp32x2 FMA (sm_103a)
#define FMA2(d, a, b, c) \
    asm("fma.rn.f32x2 %0, %1, %2, %3;" : "=l"(d) : "l"(a), "l"(b), "l"(c))
#define PACK_DUP(d, s) \
    asm("mov.b64 %0, {%1, %1};" : "=l"(d) : "r"(s))
#define UNPACK2(lo, hi, in) \
    asm("mov.b64 {%0, %1}, %2;" : "=r"(lo), "=r"(hi) : "l"(in))

// ---------------- scratch (static device globals; BSS -> zero at load) ------
__device__ int   g_cnt[N_NODES];                 // in-degree counters
__device__ int   g_bucket[(size_t)N_NODES * CAP];// per-dst neighbor lists
__device__ float g_aggr[(size_t)N_NODES * DIM];  // mean-aggregated features
__device__ float g_out[(size_t)N_NODES * DIM];   // post-linear output
__device__ float g_bnstats[2 * DIM];             // [0:64) sum, [64:128) sumsq
__device__ u64   g_bar[3];                       // generation grid barriers

// ---------------- L2-coherent loads (bypass L1 for cross-phase data) --------
__device__ __forceinline__ u64 ldcg64(const u64* p) {
    u64 v; asm volatile("ld.global.cg.u64 %0, [%1];" : "=l"(v) : "l"(p)); return v;
}
__device__ __forceinline__ int ldcg_i(const int* p) {
    int v; asm volatile("ld.global.cg.u32 %0, [%1];" : "=r"(v) : "l"(p)); return v;
}
__device__ __forceinline__ int4 ldcg_i4(const int4* p) {
    int4 v;
    asm volatile("ld.global.cg.v4.u32 {%0,%1,%2,%3}, [%4];"
                 : "=r"(v.x), "=r"(v.y), "=r"(v.z), "=r"(v.w) : "l"(p));
    return v;
}
__device__ __forceinline__ float4 ldcg_f4(const float* p) {
    float4 v;
    asm volatile("ld.global.cg.v4.f32 {%0,%1,%2,%3}, [%4];"
                 : "=f"(v.x), "=f"(v.y), "=f"(v.z), "=f"(v.w) : "l"(p));
    return v;
}

// ---------------- generation grid barrier (replay-safe, no resets) ----------
__device__ __forceinline__ void grid_barrier(int idx, int G) {
    __threadfence();                 // my writes -> device scope
    __syncthreads();                 // whole block arrived + fenced
    if (threadIdx.x == 0) {
        u64 old = atomicAdd(&g_bar[idx], 1ULL);
        u64 target = (old / (u64)G + 1ULL) * (u64)G;
        while (ldcg64(&g_bar[idx]) < target) __nanosleep(64);
    }
    __syncthreads();
}

// ---------------- THE kernel: scatter -> aggr -> gemm -> final --------------
__global__ void __launch_bounds__(256, 4) k_fused(
    const float4* __restrict__ x4, const int* __restrict__ ei,
    const float* __restrict__ w, const float* __restrict__ b,
    const float* __restrict__ gamma, const float* __restrict__ beta,
    float4* __restrict__ out4)
{
    __shared__ float sA[GEMM_BM * DIM];   // 32KB (also BN-reduction scratch)
    __shared__ float sW[DIM * DIM];       // 16KB: sW[k*64+j] = w[j*64+k]

    const int tid  = threadIdx.x;
    const int G    = gridDim.x;
    const int NT   = G * 256;
    const int gtid = blockIdx.x * 256 + tid;

    // stage W transposed (independent of all phases; overlaps P1)
    for (int idx = tid; idx < DIM * DIM; idx += 256) {
        int j = idx >> 6, k = idx & 63;
        sW[k * DIM + j] = w[idx];
    }

    // ---- P1: zero BN stats + histogram/bucket scatter ----
    if (gtid < 2 * DIM) g_bnstats[gtid] = 0.0f;
    for (int e = gtid; e < N_EDGES; e += NT) {
        int src = __ldg(ei + e);
        int dst = __ldg(ei + N_EDGES + e);
        int pos = atomicAdd(&g_cnt[dst], 1);
        if (pos < CAP) g_bucket[(size_t)dst * CAP + pos] = src;
    }
    grid_barrier(0, G);

    // ---- P2: dst-major mean aggregation (lane fixed: NT % 16 == 0) ----
    {
        const int lane = gtid & 15;
        const float4* xl = x4 + lane;
        for (int t = gtid; t < N_NODES * 16; t += NT) {
            int g = t >> 4;
            int cnt = ldcg_i(g_cnt + g);
            if (cnt > CAP) cnt = CAP;
            const int* bp = g_bucket + (size_t)g * CAP;
            float4 acc = __ldg(xl + g * (DIM / 4));      // self loop
            int i = 0;
            for (; i + 4 <= cnt; i += 4) {
                int4 s = ldcg_i4(reinterpret_cast<const int4*>(bp + i));
                float4 v0 = __ldg(xl + s.x * (DIM / 4));
                float4 v1 = __ldg(xl + s.y * (DIM / 4));
                float4 v2 = __ldg(xl + s.z * (DIM / 4));
                float4 v3 = __ldg(xl + s.w * (DIM / 4));
                acc.x += (v0.x + v1.x) + (v2.x + v3.x);
                acc.y += (v0.y + v1.y) + (v2.y + v3.y);
                acc.z += (v0.z + v1.z) + (v2.z + v3.z);
                acc.w += (v0.w + v1.w) + (v2.w + v3.w);
            }
            for (; i < cnt; i++) {
                float4 v = __ldg(xl + ldcg_i(bp + i) * (DIM / 4));
                acc.x += v.x; acc.y += v.y; acc.z += v.z; acc.w += v.w;
            }
            float inv = 1.0f / (float)(cnt + 1);
            acc.x *= inv; acc.y *= inv; acc.z *= inv; acc.w *= inv;
            reinterpret_cast<float4*>(g_aggr)[g * (DIM / 4) + lane] = acc;
        }
    }
    grid_barrier(1, G);

    // ---- P3: register-tiled f32x2 GEMM + BN partials (strided tiles) ----
    {
        const int tx = tid & 15;          // channel quad
        const int ty = tid >> 4;          // node octet
        for (int tile = blockIdx.x; tile < GEMM_NBLK; tile += G) {
            int n0 = tile * GEMM_BM;
            for (int idx = tid; idx < GEMM_BM * (DIM / 4); idx += 256) {
                int row = idx >> 4, q = idx & 15;
                int n = n0 + row;
                float4 v = (n < N_NODES)
                    ? reinterpret_cast<const float4*>(g_aggr)[n * (DIM / 4) + q]
                    : make_float4(0.f, 0.f, 0.f, 0.f);
                *reinterpret_cast<float4*>(&sA[row * DIM + q * 4]) = v;
            }
            __syncthreads();

            u64 acc01[8], acc23[8];
            #pragma unroll
            for (int i = 0; i < 8; i++) { acc01[i] = 0ULL; acc23[i] = 0ULL; }

            #pragma unroll 4
            for (int k = 0; k < DIM; k++) {
                double2 wp = *reinterpret_cast<const double2*>(&sW[k * DIM + tx * 4]);
                u64 w01 = __double_as_longlong(wp.x);
                u64 w23 = __double_as_longlong(wp.y);
                #pragma unroll
                for (int i = 0; i < 8; i++) {
                    unsigned a = *reinterpret_cast<const unsigned*>(
                        &sA[(ty * 8 + i) * DIM + k]);
                    u64 aa; PACK_DUP(aa, a);
                    FMA2(acc01[i], aa, w01, acc01[i]);
                    FMA2(acc23[i], aa, w23, acc23[i]);
                }
            }

            float4 bv = *reinterpret_cast<const float4*>(&b[tx * 4]);
            float psum[4] = {0, 0, 0, 0};
            float psq[4]  = {0, 0, 0, 0};

            #pragma unroll
            for (int i = 0; i < 8; i++) {
                int n = n0 + ty * 8 + i;
                if (n < N_NODES) {
                    unsigned r0, r1, r2, r3;
                    UNPACK2(r0, r1, acc01[i]);
                    UNPACK2(r2, r3, acc23[i]);
                    float4 o;
                    o.x = __uint_as_float(r0) + bv.x;
                    o.y = __uint_as_float(r1) + bv.y;
                    o.z = __uint_as_float(r2) + bv.z;
                    o.w = __uint_as_float(r3) + bv.w;
                    reinterpret_cast<float4*>(g_out)[n * (DIM / 4) + tx] = o;
                    psum[0] += o.x; psum[1] += o.y; psum[2] += o.z; psum[3] += o.w;
                    psq[0] += o.x * o.x; psq[1] += o.y * o.y;
                    psq[2] += o.z * o.z; psq[3] += o.w * o.w;
                }
            }

            __syncthreads();
            float (*sRed)[DIM] = reinterpret_cast<float (*)[DIM]>(sA);

            #pragma unroll
            for (int c = 0; c < 4; c++) sRed[ty][tx * 4 + c] = psum[c];
            __syncthreads();
            #pragma unroll
            for (int st = 8; st > 0; st >>= 1) {
                if (ty < st)
                    #pragma unroll
                    for (int c = 0; c < 4; c++)
                        sRed[ty][tx * 4 + c] += sRed[ty + st][tx * 4 + c];
                __syncthreads();
            }
            if (ty == 0)
                #pragma unroll
                for (int c = 0; c < 4; c++)
                    atomicAdd(&g_bnstats[tx * 4 + c], sRed[0][tx * 4 + c]);
            __syncthreads();

            #pragma unroll
            for (int c = 0; c < 4; c++) sRed[ty][tx * 4 + c] = psq[c];
            __syncthreads();
            #pragma unroll
            for (int st = 8; st > 0; st >>= 1) {
                if (ty < st)
                    #pragma unroll
                    for (int c = 0; c < 4; c++)
                        sRed[ty][tx * 4 + c] += sRed[ty + st][tx * 4 + c];
                __syncthreads();
            }
            if (ty == 0)
                #pragma unroll
                for (int c = 0; c < 4; c++)
                    atomicAdd(&g_bnstats[DIM + tx * 4 + c], sRed[0][tx * 4 + c]);
            __syncthreads();          // protect sRed before next tile's sA stage
        }
    }
    grid_barrier(2, G);

    // ---- P4: BN finalize + scale/shift + residual + relu + cnt reset ----
    {
        const int q = gtid & 15;          // fixed per thread (NT % 16 == 0)
        const float invN = 1.0f / (float)N_NODES;
        float4 s  = ldcg_f4(&g_bnstats[q * 4]);        // .cg: atomic-written
        float4 sq = ldcg_f4(&g_bnstats[DIM + q * 4]);
        float4 gm = __ldg(reinterpret_cast<const float4*>(gamma) + q);
        float4 bt = __ldg(reinterpret_cast<const float4*>(beta) + q);

        float m0 = s.x * invN, m1 = s.y * invN, m2 = s.z * invN, m3 = s.w * invN;
        float sc0 = gm.x * rsqrtf(sq.x * invN - m0 * m0 + BN_EPS);
        float sc1 = gm.y * rsqrtf(sq.y * invN - m1 * m1 + BN_EPS);
        float sc2 = gm.z * rsqrtf(sq.z * invN - m2 * m2 + BN_EPS);
        float sc3 = gm.w * rsqrtf(sq.w * invN - m3 * m3 + BN_EPS);
        float sh0 = bt.x - m0 * sc0;
        float sh1 = bt.y - m1 * sc1;
        float sh2 = bt.z - m2 * sc2;
        float sh3 = bt.w - m3 * sc3;

        for (int i = gtid; i < N_NODES * (DIM / 4); i += NT) {
            float4 o  = reinterpret_cast<const float4*>(g_out)[i];
            float4 xv = __ldg(x4 + i);
            float4 r;
            r.x = fmaxf(fmaf(o.x, sc0, sh0) + xv.x, 0.0f);
            r.y = fmaxf(fmaf(o.y, sc1, sh1) + xv.y, 0.0f);
            r.z = fmaxf(fmaf(o.z, sc2, sh2) + xv.z, 0.0f);
            r.w = fmaxf(fmaf(o.w, sc3, sh3) + xv.w, 0.0f);
            out4[i] = r;
        }
        for (int i = gtid; i < N_NODES; i += NT) g_cnt[i] = 0;  // next replay
    }
}

// ---------------- launch: one persistent kernel, occupancy-sized grid -------
extern "C" void kernel_launch(void* const* d_in, const int* in_sizes, int n_in,
                              void* d_out, int out_size) {
    const float* x     = (const float*)d_in[0];
    const int*   ei    = (const int*)d_in[1];
    const float* w     = (const float*)d_in[2];
    const float* b     = (const float*)d_in[3];
    const float* gamma = (const float*)d_in[4];
    const float* beta  = (const float*)d_in[5];
    float*       out   = (float*)d_out;

    int dev = 0;
    cudaGetDevice(&dev);
    int nsm = 0;
    cudaDeviceGetAttribute(&nsm, cudaDevAttrMultiProcessorCount, dev);
    int bpm = 0;
    cudaOccupancyMaxActiveBlocksPerMultiprocessor(&bpm, k_fused, 256, 0);
    if (bpm < 1) bpm = 1;
    if (nsm < 1) nsm = 1;
    int grid = nsm * bpm;           // provably co-resident -> barrier-safe

    k_fused<<<grid, 256>>>((const float4*)x, ei, w, b, gamma, beta,
                           (float4*)out);
}

// round 14
// speedup vs baseline: 1.1078x; 1.1078x over previous
#include <cuda_runtime.h>
#include <cstdint>

#define N_NODES 100000
#define N_EDGES 1000000
#define DIM 64
#define BN_EPS 1e-5f
#define CAP 96                                          // max in-degree bucket

#define GEMM_BM 128                                     // nodes per block
#define GEMM_NBLK ((N_NODES + GEMM_BM - 1) / GEMM_BM)   // 782

typedef unsigned long long u64;

// packed fp32x2 FMA (sm_103a): d = a*b + c on both 32-bit halves
#define FMA2(d, a, b, c) \
    asm("fma.rn.f32x2 %0, %1, %2, %3;" : "=l"(d) : "l"(a), "l"(b), "l"(c))
#define PACK_DUP(d, s) \
    asm("mov.b64 %0, {%1, %1};" : "=l"(d) : "r"(s))
#define UNPACK2(lo, hi, in) \
    asm("mov.b64 {%0, %1}, %2;" : "=r"(lo), "=r"(hi) : "l"(in))

// ---------------- scratch (static device globals; BSS -> zero at load) ------
__device__ int   g_cnt[N_NODES];                 // in-degree counters
__device__ int   g_bucket[(size_t)N_NODES * CAP];// per-dst neighbor lists
__device__ float g_aggr[(size_t)N_NODES * DIM];  // mean-aggregated features
__device__ float g_out[(size_t)N_NODES * DIM];   // post-linear output
__device__ float g_bnstats[2 * DIM];             // [0:64) sum, [64:128) sumsq

// ---------------- kernel 1: fused histogram + bucket scatter ----------------
__global__ void k_scatter(const int* __restrict__ ei) {
    int e = blockIdx.x * blockDim.x + threadIdx.x;
    if (blockIdx.x == 0 && threadIdx.x < 2 * DIM) g_bnstats[threadIdx.x] = 0.0f;
    if (e >= N_EDGES) return;
    int src = ei[e];
    int dst = ei[N_EDGES + e];
    int pos = atomicAdd(&g_cnt[dst], 1);
    if (pos < CAP) g_bucket[(size_t)dst * CAP + pos] = src;
}

// ---------------- kernel 2: dst-major aggregation, predicated chunks --------
// Always processes full int4 chunks (bucket rows are CAP-capacity, reads past
// cnt are in-bounds; stale slots hold valid node ids -> safe to gather).
// Contributions beyond cnt are masked with fmaf(v, 0, acc). This removes the
// serial dependent-tail chain (~2 x L2-latency per node) entirely.
__global__ void k_aggr(const float4* __restrict__ x4) {
    int g    = blockIdx.x * (blockDim.x >> 4) + (threadIdx.x >> 4);
    int lane = threadIdx.x & 15;
    if (g >= N_NODES) return;
    int cnt = __ldg(g_cnt + g);
    if (cnt > CAP) cnt = CAP;                        // safety clamp
    const int* bp = g_bucket + (size_t)g * CAP;
    const float4* xl = x4 + lane;
    float4 acc = __ldg(xl + g * (DIM / 4));          // self loop
    for (int i = 0; i < cnt; i += 4) {
        int4 s = *reinterpret_cast<const int4*>(bp + i);   // always in-bounds
        float4 v0 = __ldg(xl + s.x * (DIM / 4));
        float4 v1 = __ldg(xl + s.y * (DIM / 4));
        float4 v2 = __ldg(xl + s.z * (DIM / 4));
        float4 v3 = __ldg(xl + s.w * (DIM / 4));
        float m1 = (i + 1 < cnt) ? 1.0f : 0.0f;      // m0 == 1 (i < cnt)
        float m2 = (i + 2 < cnt) ? 1.0f : 0.0f;
        float m3 = (i + 3 < cnt) ? 1.0f : 0.0f;
        acc.x += v0.x; acc.y += v0.y; acc.z += v0.z; acc.w += v0.w;
        acc.x = fmaf(v1.x, m1, acc.x); acc.y = fmaf(v1.y, m1, acc.y);
        acc.z = fmaf(v1.z, m1, acc.z); acc.w = fmaf(v1.w, m1, acc.w);
        acc.x = fmaf(v2.x, m2, acc.x); acc.y = fmaf(v2.y, m2, acc.y);
        acc.z = fmaf(v2.z, m2, acc.z); acc.w = fmaf(v2.w, m2, acc.w);
        acc.x = fmaf(v3.x, m3, acc.x); acc.y = fmaf(v3.y, m3, acc.y);
        acc.z = fmaf(v3.z, m3, acc.z); acc.w = fmaf(v3.w, m3, acc.w);
    }
    float inv = 1.0f / (float)(cnt + 1);
    acc.x *= inv; acc.y *= inv; acc.z *= inv; acc.w *= inv;
    reinterpret_cast<float4*>(g_aggr)[g * (DIM / 4) + lane] = acc;
}

// ---------------- kernel 3: register-tiled GEMM (f32x2 FMA) + BN partials ---
__global__ void __launch_bounds__(256) k_gemm(const float* __restrict__ w,
                                              const float* __restrict__ b) {
    __shared__ float sA[GEMM_BM * DIM];   // sA[n_local*64 + k]
    __shared__ float sW[DIM * DIM];       // sW[k*64 + j] = w[j*64 + k]

    int tid = threadIdx.x;
    int tx = tid & 15;          // channel quad
    int ty = tid >> 4;          // node octet
    int n0 = blockIdx.x * GEMM_BM;

    for (int idx = tid; idx < DIM * DIM; idx += 256) {
        int j = idx >> 6, k = idx & 63;
        sW[k * DIM + j] = w[idx];
    }
    for (int idx = tid; idx < GEMM_BM * (DIM / 4); idx += 256) {
        int row = idx >> 4, q = idx & 15;
        int n = n0 + row;
        float4 v = (n < N_NODES)
            ? reinterpret_cast<const float4*>(g_aggr)[n * (DIM / 4) + q]
            : make_float4(0.f, 0.f, 0.f, 0.f);
        *reinterpret_cast<float4*>(&sA[row * DIM + q * 4]) = v;
    }
    __syncthreads();

    u64 acc01[8], acc23[8];
    #pragma unroll
    for (int i = 0; i < 8; i++) { acc01[i] = 0ULL; acc23[i] = 0ULL; }

    #pragma unroll 4
    for (int k = 0; k < DIM; k++) {
        double2 wp = *reinterpret_cast<const double2*>(&sW[k * DIM + tx * 4]);
        u64 w01 = __double_as_longlong(wp.x);
        u64 w23 = __double_as_longlong(wp.y);
        #pragma unroll
        for (int i = 0; i < 8; i++) {
            unsigned a = *reinterpret_cast<const unsigned*>(
                &sA[(ty * 8 + i) * DIM + k]);
            u64 aa; PACK_DUP(aa, a);
            FMA2(acc01[i], aa, w01, acc01[i]);
            FMA2(acc23[i], aa, w23, acc23[i]);
        }
    }

    float4 bv = *reinterpret_cast<const float4*>(&b[tx * 4]);
    float psum[4] = {0, 0, 0, 0};
    float psq[4]  = {0, 0, 0, 0};

    #pragma unroll
    for (int i = 0; i < 8; i++) {
        int n = n0 + ty * 8 + i;
        if (n < N_NODES) {
            unsigned r0, r1, r2, r3;
            UNPACK2(r0, r1, acc01[i]);
            UNPACK2(r2, r3, acc23[i]);
            float4 o;
            o.x = __uint_as_float(r0) + bv.x;
            o.y = __uint_as_float(r1) + bv.y;
            o.z = __uint_as_float(r2) + bv.z;
            o.w = __uint_as_float(r3) + bv.w;
            reinterpret_cast<float4*>(g_out)[n * (DIM / 4) + tx] = o;
            psum[0] += o.x; psum[1] += o.y; psum[2] += o.z; psum[3] += o.w;
            psq[0] += o.x * o.x; psq[1] += o.y * o.y;
            psq[2] += o.z * o.z; psq[3] += o.w * o.w;
        }
    }

    __syncthreads();
    float (*sRed)[DIM] = reinterpret_cast<float (*)[DIM]>(sA);

    #pragma unroll
    for (int c = 0; c < 4; c++) sRed[ty][tx * 4 + c] = psum[c];
    __syncthreads();
    #pragma unroll
    for (int st = 8; st > 0; st >>= 1) {
        if (ty < st)
            #pragma unroll
            for (int c = 0; c < 4; c++)
                sRed[ty][tx * 4 + c] += sRed[ty + st][tx * 4 + c];
        __syncthreads();
    }
    if (ty == 0)
        #pragma unroll
        for (int c = 0; c < 4; c++)
            atomicAdd(&g_bnstats[tx * 4 + c], sRed[0][tx * 4 + c]);
    __syncthreads();

    #pragma unroll
    for (int c = 0; c < 4; c++) sRed[ty][tx * 4 + c] = psq[c];
    __syncthreads();
    #pragma unroll
    for (int st = 8; st > 0; st >>= 1) {
        if (ty < st)
            #pragma unroll
            for (int c = 0; c < 4; c++)
                sRed[ty][tx * 4 + c] += sRed[ty + st][tx * 4 + c];
        __syncthreads();
    }
    if (ty == 0)
        #pragma unroll
        for (int c = 0; c < 4; c++)
            atomicAdd(&g_bnstats[DIM + tx * 4 + c], sRed[0][tx * 4 + c]);
}

// ---------------- kernel 4: BN finalize + scale/shift + residual + relu -----
__global__ void k_final(const float4* __restrict__ x4,
                        const float4* __restrict__ gamma4,
                        const float4* __restrict__ beta4,
                        float4* __restrict__ out4) {
    int i = blockIdx.x * blockDim.x + threadIdx.x;
    if (i < N_NODES) g_cnt[i] = 0;                   // reset for next launch
    if (i >= N_NODES * (DIM / 4)) return;
    int q = i & 15;
    const float invN = 1.0f / (float)N_NODES;

    float4 s  = *reinterpret_cast<const float4*>(&g_bnstats[q * 4]);
    float4 sq = *reinterpret_cast<const float4*>(&g_bnstats[DIM + q * 4]);
    float4 gm = __ldg(gamma4 + q);
    float4 bt = __ldg(beta4 + q);

    float m0 = s.x * invN, m1 = s.y * invN, m2 = s.z * invN, m3 = s.w * invN;
    float sc0 = gm.x * rsqrtf(sq.x * invN - m0 * m0 + BN_EPS);
    float sc1 = gm.y * rsqrtf(sq.y * invN - m1 * m1 + BN_EPS);
    float sc2 = gm.z * rsqrtf(sq.z * invN - m2 * m2 + BN_EPS);
    float sc3 = gm.w * rsqrtf(sq.w * invN - m3 * m3 + BN_EPS);
    float sh0 = bt.x - m0 * sc0;
    float sh1 = bt.y - m1 * sc1;
    float sh2 = bt.z - m2 * sc2;
    float sh3 = bt.w - m3 * sc3;

    float4 o  = reinterpret_cast<const float4*>(g_out)[i];
    float4 xv = x4[i];
    float4 r;
    r.x = fmaxf(fmaf(o.x, sc0, sh0) + xv.x, 0.0f);
    r.y = fmaxf(fmaf(o.y, sc1, sh1) + xv.y, 0.0f);
    r.z = fmaxf(fmaf(o.z, sc2, sh2) + xv.z, 0.0f);
    r.w = fmaxf(fmaf(o.w, sc3, sh3) + xv.w, 0.0f);
    out4[i] = r;
}

// ---------------- launch -----------------------------------------------------
extern "C" void kernel_launch(void* const* d_in, const int* in_sizes, int n_in,
                              void* d_out, int out_size) {
    const float* x     = (const float*)d_in[0];
    const int*   ei    = (const int*)d_in[1];
    const float* w     = (const float*)d_in[2];
    const float* b     = (const float*)d_in[3];
    const float* gamma = (const float*)d_in[4];
    const float* beta  = (const float*)d_in[5];
    float*       out   = (float*)d_out;

    const int vec = N_NODES * (DIM / 4);

    k_scatter<<<(N_EDGES + 255) / 256, 256>>>(ei);
    k_aggr<<<(N_NODES * 16 + 255) / 256, 256>>>((const float4*)x);
    k_gemm<<<GEMM_NBLK, 256>>>(w, b);
    k_final<<<(vec + 255) / 256, 256>>>((const float4*)x,
                                        (const float4*)gamma,
                                        (const float4*)beta,
                                        (float4*)out);
}

// round 15
// speedup vs baseline: 1.1134x; 1.0051x over previous
#include <cuda_runtime.h>
#include <cstdint>

#define N_NODES 100000
#define N_EDGES 1000000
#define DIM 64
#define BN_EPS 1e-5f
#define CAP 96                                          // max in-degree bucket

#define GEMM_BM 128                                     // nodes per block
#define GEMM_NBLK ((N_NODES + GEMM_BM - 1) / GEMM_BM)   // 782

typedef unsigned long long u64;

// packed fp32x2 FMA (sm_103a): d = a*b + c on both 32-bit halves
#define FMA2(d, a, b, c) \
    asm("fma.rn.f32x2 %0, %1, %2, %3;" : "=l"(d) : "l"(a), "l"(b), "l"(c))
#define PACK_DUP(d, s) \
    asm("mov.b64 %0, {%1, %1};" : "=l"(d) : "r"(s))
#define UNPACK2(lo, hi, in) \
    asm("mov.b64 {%0, %1}, %2;" : "=r"(lo), "=r"(hi) : "l"(in))

// ---------------- scratch (static device globals; BSS -> zero at load) ------
__device__ int   g_cnt[N_NODES];                 // in-degree counters
__device__ int   g_bucket[(size_t)N_NODES * CAP];// per-dst neighbor lists
__device__ float g_aggr[(size_t)N_NODES * DIM];  // mean-aggregated features
__device__ float g_out[(size_t)N_NODES * DIM];   // post-linear output
__device__ float g_bnstats[2 * DIM];             // [0:64) sum, [64:128) sumsq

// ---------------- kernel 1: fused histogram + bucket scatter ----------------
__global__ void k_scatter(const int* __restrict__ ei) {
    int e = blockIdx.x * blockDim.x + threadIdx.x;
    if (blockIdx.x == 0 && threadIdx.x < 2 * DIM) g_bnstats[threadIdx.x] = 0.0f;
    if (e < N_EDGES) {
        int src = ei[e];
        int dst = ei[N_EDGES + e];
        int pos = atomicAdd(&g_cnt[dst], 1);
        if (pos < CAP) g_bucket[(size_t)dst * CAP + pos] = src;
    }
#if __CUDA_ARCH__ >= 900
    cudaTriggerProgrammaticLaunchCompletion();
#endif
}

// ---------------- kernel 2: dst-major aggregation (PDL secondary) -----------
__global__ void k_aggr(const float4* __restrict__ x4) {
    int g    = blockIdx.x * (blockDim.x >> 4) + (threadIdx.x >> 4);
    int lane = threadIdx.x & 15;
    // preamble independent of scatter: self-loop row load can't start (same
    // data region is fine — x4 is input-only), so issue it before the sync.
    const float4* xl = x4 + lane;
    float4 acc = make_float4(0.f, 0.f, 0.f, 0.f);
    bool act = (g < N_NODES);
    if (act) acc = __ldg(xl + g * (DIM / 4));        // self loop (input only)
#if __CUDA_ARCH__ >= 900
    cudaGridDependencySynchronize();                 // wait: g_cnt/g_bucket
#endif
    if (!act) return;
    int cnt = __ldg(g_cnt + g);
    if (cnt > CAP) cnt = CAP;                        // safety clamp
    const int* bp = g_bucket + (size_t)g * CAP;
    int i = 0;
    for (; i + 4 <= cnt; i += 4) {
        int4 s = *reinterpret_cast<const int4*>(bp + i);
        float4 v0 = __ldg(xl + s.x * (DIM / 4));
        float4 v1 = __ldg(xl + s.y * (DIM / 4));
        float4 v2 = __ldg(xl + s.z * (DIM / 4));
        float4 v3 = __ldg(xl + s.w * (DIM / 4));
        acc.x += (v0.x + v1.x) + (v2.x + v3.x);
        acc.y += (v0.y + v1.y) + (v2.y + v3.y);
        acc.z += (v0.z + v1.z) + (v2.z + v3.z);
        acc.w += (v0.w + v1.w) + (v2.w + v3.w);
    }
    for (; i < cnt; i++) {
        float4 v = __ldg(xl + __ldg(bp + i) * (DIM / 4));
        acc.x += v.x; acc.y += v.y; acc.z += v.z; acc.w += v.w;
    }
    float inv = 1.0f / (float)(cnt + 1);
    acc.x *= inv; acc.y *= inv; acc.z *= inv; acc.w *= inv;
    reinterpret_cast<float4*>(g_aggr)[g * (DIM / 4) + lane] = acc;
#if __CUDA_ARCH__ >= 900
    cudaTriggerProgrammaticLaunchCompletion();
#endif
}

// ---------------- kernel 3: f32x2 GEMM + BN partials (PDL secondary) --------
// Preamble (sW staging from input w) overlaps k_aggr's tail.
__global__ void __launch_bounds__(256) k_gemm(const float* __restrict__ w,
                                              const float* __restrict__ b) {
    __shared__ float sA[GEMM_BM * DIM];   // sA[n_local*64 + k]
    __shared__ float sW[DIM * DIM];       // sW[k*64 + j] = w[j*64 + k]

    int tid = threadIdx.x;
    int tx = tid & 15;          // channel quad
    int ty = tid >> 4;          // node octet
    int n0 = blockIdx.x * GEMM_BM;

    for (int idx = tid; idx < DIM * DIM; idx += 256) {   // input-only: pre-sync
        int j = idx >> 6, k = idx & 63;
        sW[k * DIM + j] = w[idx];
    }
    float4 bv = *reinterpret_cast<const float4*>(&b[tx * 4]);  // input-only

#if __CUDA_ARCH__ >= 900
    cudaGridDependencySynchronize();                 // wait: g_aggr
#endif

    for (int idx = tid; idx < GEMM_BM * (DIM / 4); idx += 256) {
        int row = idx >> 4, q = idx & 15;
        int n = n0 + row;
        float4 v = (n < N_NODES)
            ? reinterpret_cast<const float4*>(g_aggr)[n * (DIM / 4) + q]
            : make_float4(0.f, 0.f, 0.f, 0.f);
        *reinterpret_cast<float4*>(&sA[row * DIM + q * 4]) = v;
    }
    __syncthreads();

    u64 acc01[8], acc23[8];
    #pragma unroll
    for (int i = 0; i < 8; i++) { acc01[i] = 0ULL; acc23[i] = 0ULL; }

    #pragma unroll 4
    for (int k = 0; k < DIM; k++) {
        double2 wp = *reinterpret_cast<const double2*>(&sW[k * DIM + tx * 4]);
        u64 w01 = __double_as_longlong(wp.x);
        u64 w23 = __double_as_longlong(wp.y);
        #pragma unroll
        for (int i = 0; i < 8; i++) {
            unsigned a = *reinterpret_cast<const unsigned*>(
                &sA[(ty * 8 + i) * DIM + k]);
            u64 aa; PACK_DUP(aa, a);
            FMA2(acc01[i], aa, w01, acc01[i]);
            FMA2(acc23[i], aa, w23, acc23[i]);
        }
    }

    float psum[4] = {0, 0, 0, 0};
    float psq[4]  = {0, 0, 0, 0};

    #pragma unroll
    for (int i = 0; i < 8; i++) {
        int n = n0 + ty * 8 + i;
        if (n < N_NODES) {
            unsigned r0, r1, r2, r3;
            UNPACK2(r0, r1, acc01[i]);
            UNPACK2(r2, r3, acc23[i]);
            float4 o;
            o.x = __uint_as_float(r0) + bv.x;
            o.y = __uint_as_float(r1) + bv.y;
            o.z = __uint_as_float(r2) + bv.z;
            o.w = __uint_as_float(r3) + bv.w;
            reinterpret_cast<float4*>(g_out)[n * (DIM / 4) + tx] = o;
            psum[0] += o.x; psum[1] += o.y; psum[2] += o.z; psum[3] += o.w;
            psq[0] += o.x * o.x; psq[1] += o.y * o.y;
            psq[2] += o.z * o.z; psq[3] += o.w * o.w;
        }
    }

    __syncthreads();
    float (*sRed)[DIM] = reinterpret_cast<float (*)[DIM]>(sA);

    #pragma unroll
    for (int c = 0; c < 4; c++) sRed[ty][tx * 4 + c] = psum[c];
    __syncthreads();
    #pragma unroll
    for (int st = 8; st > 0; st >>= 1) {
        if (ty < st)
            #pragma unroll
            for (int c = 0; c < 4; c++)
                sRed[ty][tx * 4 + c] += sRed[ty + st][tx * 4 + c];
        __syncthreads();
    }
    if (ty == 0)
        #pragma unroll
        for (int c = 0; c < 4; c++)
            atomicAdd(&g_bnstats[tx * 4 + c], sRed[0][tx * 4 + c]);
    __syncthreads();

    #pragma unroll
    for (int c = 0; c < 4; c++) sRed[ty][tx * 4 + c] = psq[c];
    __syncthreads();
    #pragma unroll
    for (int st = 8; st > 0; st >>= 1) {
        if (ty < st)
            #pragma unroll
            for (int c = 0; c < 4; c++)
                sRed[ty][tx * 4 + c] += sRed[ty + st][tx * 4 + c];
        __syncthreads();
    }
    if (ty == 0)
        #pragma unroll
        for (int c = 0; c < 4; c++)
            atomicAdd(&g_bnstats[DIM + tx * 4 + c], sRed[0][tx * 4 + c]);
#if __CUDA_ARCH__ >= 900
    cudaTriggerProgrammaticLaunchCompletion();
#endif
}

// ---------------- kernel 4: BN finalize + residual + relu (PDL secondary) ---
// Preamble loads x/gamma/beta (inputs) before syncing on g_bnstats/g_out.
__global__ void k_final(const float4* __restrict__ x4,
                        const float4* __restrict__ gamma4,
                        const float4* __restrict__ beta4,
                        float4* __restrict__ out4) {
    int i = blockIdx.x * blockDim.x + threadIdx.x;
    int q = i & 15;
    bool act = (i < N_NODES * (DIM / 4));
    float4 xv = make_float4(0.f, 0.f, 0.f, 0.f);
    float4 gm = make_float4(0.f, 0.f, 0.f, 0.f);
    float4 bt = make_float4(0.f, 0.f, 0.f, 0.f);
    if (act) {
        xv = __ldg(x4 + i);
        gm = __ldg(gamma4 + q);
        bt = __ldg(beta4 + q);
    }
#if __CUDA_ARCH__ >= 900
    cudaGridDependencySynchronize();                 // wait: g_bnstats/g_out
#endif
    if (i < N_NODES) g_cnt[i] = 0;                   // reset for next launch
    if (!act) return;
    const float invN = 1.0f / (float)N_NODES;

    float4 s  = *reinterpret_cast<const float4*>(&g_bnstats[q * 4]);
    float4 sq = *reinterpret_cast<const float4*>(&g_bnstats[DIM + q * 4]);

    float m0 = s.x * invN, m1 = s.y * invN, m2 = s.z * invN, m3 = s.w * invN;
    float sc0 = gm.x * rsqrtf(sq.x * invN - m0 * m0 + BN_EPS);
    float sc1 = gm.y * rsqrtf(sq.y * invN - m1 * m1 + BN_EPS);
    float sc2 = gm.z * rsqrtf(sq.z * invN - m2 * m2 + BN_EPS);
    float sc3 = gm.w * rsqrtf(sq.w * invN - m3 * m3 + BN_EPS);
    float sh0 = bt.x - m0 * sc0;
    float sh1 = bt.y - m1 * sc1;
    float sh2 = bt.z - m2 * sc2;
    float sh3 = bt.w - m3 * sc3;

    float4 o = reinterpret_cast<const float4*>(g_out)[i];
    float4 r;
    r.x = fmaxf(fmaf(o.x, sc0, sh0) + xv.x, 0.0f);
    r.y = fmaxf(fmaf(o.y, sc1, sh1) + xv.y, 0.0f);
    r.z = fmaxf(fmaf(o.z, sc2, sh2) + xv.z, 0.0f);
    r.w = fmaxf(fmaf(o.w, sc3, sh3) + xv.w, 0.0f);
    out4[i] = r;
}

// ---------------- launch: PDL chain ------------------------------------------
template <typename... Args>
static void launch_pdl(void (*kern)(Args...), int grid, int block, bool pdl,
                       Args... args) {
    cudaLaunchConfig_t cfg = {};
    cfg.gridDim  = dim3(grid, 1, 1);
    cfg.blockDim = dim3(block, 1, 1);
    cudaLaunchAttribute attr[1];
    if (pdl) {
        attr[0].id = cudaLaunchAttributeProgrammaticStreamSerialization;
        attr[0].val.programmaticStreamSerializationAllowed = 1;
        cfg.attrs = attr;
        cfg.numAttrs = 1;
    }
    cudaLaunchKernelEx(&cfg, kern, args...);
}

extern "C" void kernel_launch(void* const* d_in, const int* in_sizes, int n_in,
                              void* d_out, int out_size) {
    const float* x     = (const float*)d_in[0];
    const int*   ei    = (const int*)d_in[1];
    const float* w     = (const float*)d_in[2];
    const float* b     = (const float*)d_in[3];
    const float* gamma = (const float*)d_in[4];
    const float* beta  = (const float*)d_in[5];
    float*       out   = (float*)d_out;

    const int vec = N_NODES * (DIM / 4);

    launch_pdl(k_scatter, (N_EDGES + 255) / 256, 256, false, ei);
    launch_pdl(k_aggr, (N_NODES * 16 + 255) / 256, 256, true,
               (const float4*)x);
    launch_pdl(k_gemm, GEMM_NBLK, 256, true, w, b);
    launch_pdl(k_final, (vec + 255) / 256, 256, true,
               (const float4*)x, (const float4*)gamma,
               (const float4*)beta, (float4*)out);
}